// round 6
// baseline (speedup 1.0000x reference)
#include <cuda_runtime.h>

#define NN 50000
#define NE 600000
#define HID 128
#define NG 64
#define NBLK 196   // ceil(50000/256)

// ---- device scratch (no allocations allowed) ----
__device__ int   g_cnt[3][NN];
__device__ float g_dinv[3][NN];
__device__ int   g_off[NN + 1];
__device__ int   g_cur[NN];
__device__ int   g_bsum[NBLK];
__device__ int   g_bpre[NBLK];
__device__ unsigned g_csr[NE];
__device__ __align__(16) float g_h[3][NN * HID];  // 0: gemm out, 1/2: activations
__device__ __align__(16) float g_pool[NG * HID];
__device__ float g_pcnt[NG];

// ---------------- init ----------------
__global__ void k_zero() {
    int i = blockIdx.x * blockDim.x + threadIdx.x;
    if (i < NN) { g_cnt[0][i] = 0; g_cnt[1][i] = 0; g_cnt[2][i] = 0; }
    if (i < NG * HID) g_pool[i] = 0.0f;
    if (i < NG) g_pcnt[i] = 0.0f;
}

// ---------------- degree histogram ----------------
__global__ void k_hist(const int* __restrict__ ei,
                       const int* __restrict__ em) {
    int e = blockIdx.x * blockDim.x + threadIdx.x;
    if (e >= NE) return;
    int d = ei[NE + e];
    int m = em[e];
    atomicAdd(&g_cnt[0][d], 1);
    if (m == 1) atomicAdd(&g_cnt[1][d], 1);
    else if (m == 2) atomicAdd(&g_cnt[2][d], 1);
}

// ---------------- scan pass A: per-block sums ----------------
__global__ void k_scanA() {
    int i = blockIdx.x * 256 + threadIdx.x;
    int lane = threadIdx.x & 31, warp = threadIdx.x >> 5;
    int v = (i < NN) ? g_cnt[0][i] : 0;
#pragma unroll
    for (int o = 16; o; o >>= 1) v += __shfl_xor_sync(0xFFFFFFFFu, v, o);
    __shared__ int ws[8];
    if (lane == 0) ws[warp] = v;
    __syncthreads();
    if (threadIdx.x == 0) {
        int s = 0;
#pragma unroll
        for (int j = 0; j < 8; j++) s += ws[j];
        g_bsum[blockIdx.x] = s;
    }
}

// ---------------- scan pass B: scan 196 block sums (1 block) ----------------
__global__ void k_scanB() {
    __shared__ int sh[256];
    int t = threadIdx.x;
    int v = (t < NBLK) ? g_bsum[t] : 0;
    sh[t] = v;
    __syncthreads();
    for (int d = 1; d < 256; d <<= 1) {
        int u = (t >= d) ? sh[t - d] : 0;
        __syncthreads();
        sh[t] += u;
        __syncthreads();
    }
    if (t < NBLK) g_bpre[t] = sh[t] - v;          // exclusive
    if (t == NBLK - 1) g_off[NN] = sh[t];         // total
}

// ---------------- scan pass C: local scan + apply prefix + dinv ----------------
__global__ void k_scanC() {
    int i = blockIdx.x * 256 + threadIdx.x;
    int lane = threadIdx.x & 31, warp = threadIdx.x >> 5;
    int v = (i < NN) ? g_cnt[0][i] : 0;
    int incl = v;
#pragma unroll
    for (int o = 1; o < 32; o <<= 1) {
        int t = __shfl_up_sync(0xFFFFFFFFu, incl, o);
        if (lane >= o) incl += t;
    }
    __shared__ int ws[8];
    if (lane == 31) ws[warp] = incl;
    __syncthreads();
    if (warp == 0 && lane < 8) {
        int s = ws[lane];
        int si = s;
#pragma unroll
        for (int o = 1; o < 8; o <<= 1) {
            int t = __shfl_up_sync(0xFFu, si, o);
            if (lane >= o) si += t;
        }
        ws[lane] = si - s;   // exclusive warp prefix
    }
    __syncthreads();
    if (i < NN) {
        int excl = (incl - v) + ws[warp] + g_bpre[blockIdx.x];
        g_off[i] = excl;
        g_cur[i] = excl;
        g_dinv[0][i] = rsqrtf((float)(v + 1));
        g_dinv[1][i] = rsqrtf((float)(g_cnt[1][i] + 1));
        g_dinv[2][i] = rsqrtf((float)(g_cnt[2][i] + 1));
    }
}

// ---------------- CSR scatter ----------------
__global__ void k_scatter(const int* __restrict__ ei,
                          const int* __restrict__ em) {
    int e = blockIdx.x * blockDim.x + threadIdx.x;
    if (e >= NE) return;
    int s = ei[e];
    int d = ei[NE + e];
    int m = em[e];
    int pos = atomicAdd(&g_cur[d], 1);
    g_csr[pos] = (unsigned)s | ((unsigned)m << 16);   // s < 50000 < 2^16
}

// ---------------- packed f32x2 FMA helpers ----------------
union F2 { float2 f; unsigned long long u; };
union WV { float4 f4; unsigned long long u[2]; };

#define FFMA2(d, a, b) \
    asm("fma.rn.f32x2 %0, %1, %2, %0;" : "+l"((d).u) : "l"((a).u), "l"((b).u))

// ---------------- GEMM: g_h[0] = IN @ W  (N x 128 @ 128 x 128) ----------------
// Outer-product SGEMM: 256 threads, block tile 128 rows x 128 cols,
// thread tile 8x8 (32 F2 accs). X stored k-major, duplicated (a,a) -> FFMA2
// with zero packing. 38 issue slots per 64 FMA -> fma-pipe bound.
__global__ void __launch_bounds__(256, 3)
k_gemm(int inSel,              // -1: external X, else g_h[inSel]
       const float* __restrict__ Xext,
       const float* __restrict__ W) {
    __shared__ float Ws[32][HID];       // 16KB  [k][col]
    __shared__ float Xs2[32][256];      // 32KB  [k][2r]=[k][2r+1]=X[row][k]
    const float* X = (inSel < 0) ? Xext : g_h[inSel];

    int tid = threadIdx.x;
    int tx  = tid & 15;        // col group: cols tx*8..+8
    int ty  = tid >> 4;        // row group: rows ty*8..+8
    int rowBase = blockIdx.x * 128;

    F2 acc[8][4];
#pragma unroll
    for (int r = 0; r < 8; r++)
#pragma unroll
        for (int j = 0; j < 4; j++) acc[r][j].f = make_float2(0.f, 0.f);

    for (int kt = 0; kt < HID; kt += 32) {
        // W tile 32x128: 1024 float4, 4/thread, coalesced
#pragma unroll
        for (int i = 0; i < 4; i++) {
            int j = tid + i * 256;
            int kr = j >> 5, kc = (j & 31) * 4;
            *(float4*)&Ws[kr][kc] = *(const float4*)&W[(size_t)(kt + kr) * HID + kc];
        }
        // X tile 128 rows x 32 k, transposed+duplicated.
        // j row-minor: warp = 32 consecutive rows, same kq -> conflict-free STS.64
#pragma unroll
        for (int i = 0; i < 4; i++) {
            int j = tid + i * 256;          // 0..1023
            int row = j & 127, kq = (j >> 7) * 4;
            int grow = rowBase + row;
            float4 v = make_float4(0.f, 0.f, 0.f, 0.f);
            if (grow < NN) v = *(const float4*)&X[(size_t)grow * HID + kt + kq];
            *(float2*)&Xs2[kq + 0][2 * row] = make_float2(v.x, v.x);
            *(float2*)&Xs2[kq + 1][2 * row] = make_float2(v.y, v.y);
            *(float2*)&Xs2[kq + 2][2 * row] = make_float2(v.z, v.z);
            *(float2*)&Xs2[kq + 3][2 * row] = make_float2(v.w, v.w);
        }
        __syncthreads();

#pragma unroll 4
        for (int k = 0; k < 32; k++) {
            F2 b[4];
            WV bb0, bb1;
            bb0.f4 = *(float4*)&Ws[k][tx * 8];
            bb1.f4 = *(float4*)&Ws[k][tx * 8 + 4];
            b[0].u = bb0.u[0]; b[1].u = bb0.u[1];
            b[2].u = bb1.u[0]; b[3].u = bb1.u[1];
#pragma unroll
            for (int rr = 0; rr < 4; rr++) {
                WV av;
                av.f4 = *(float4*)&Xs2[k][ty * 16 + rr * 4];  // (a,a,a',a')
                F2 a0, a1;
                a0.u = av.u[0]; a1.u = av.u[1];
#pragma unroll
                for (int j = 0; j < 4; j++) FFMA2(acc[rr * 2][j], a0, b[j]);
#pragma unroll
                for (int j = 0; j < 4; j++) FFMA2(acc[rr * 2 + 1][j], a1, b[j]);
            }
        }
        __syncthreads();
    }

#pragma unroll
    for (int r = 0; r < 8; r++) {
        int row = rowBase + ty * 8 + r;
        if (row < NN) {
            float4 o0, o1;
            o0.x = acc[r][0].f.x; o0.y = acc[r][0].f.y;
            o0.z = acc[r][1].f.x; o0.w = acc[r][1].f.y;
            o1.x = acc[r][2].f.x; o1.y = acc[r][2].f.y;
            o1.z = acc[r][3].f.x; o1.w = acc[r][3].f.y;
            *(float4*)&g_h[0][(size_t)row * HID + tx * 8]     = o0;
            *(float4*)&g_h[0][(size_t)row * HID + tx * 8 + 4] = o1;
        }
    }
}

// ---------------- aggregation: warp per node ----------------
__global__ void k_agg(int layer, int outSel,
                      const float* __restrict__ bias,
                      int mode, int do_relu,
                      int doPool, const int* __restrict__ batch) {
    int wi = (blockIdx.x * blockDim.x + threadIdx.x) >> 5;
    if (wi >= NN) return;
    int lane = threadIdx.x & 31;

    const float* dinv = g_dinv[layer];
    float di = dinv[wi];
    int e0 = g_off[wi], e1 = g_off[wi + 1];

    float ax = 0.f, ay = 0.f, az = 0.f, aw = 0.f;
    for (int e = e0; e < e1; e++) {
        unsigned p = g_csr[e];
        int m = (int)(p >> 16);
        if (mode == 0 || m == mode) {
            int s = (int)(p & 0xFFFFu);
            float c = di * dinv[s];
            float4 hv = *(const float4*)&g_h[0][(size_t)s * HID + lane * 4];
            ax += c * hv.x; ay += c * hv.y; az += c * hv.z; aw += c * hv.w;
        }
    }
    float4 hs = *(const float4*)&g_h[0][(size_t)wi * HID + lane * 4];
    float c2 = di * di;
    ax += c2 * hs.x; ay += c2 * hs.y; az += c2 * hs.z; aw += c2 * hs.w;

    float4 bv = *(const float4*)&bias[lane * 4];
    ax += bv.x; ay += bv.y; az += bv.z; aw += bv.w;

    if (do_relu) {
        ax = fmaxf(ax, 0.f); ay = fmaxf(ay, 0.f);
        az = fmaxf(az, 0.f); aw = fmaxf(aw, 0.f);
    }
    float4 o; o.x = ax; o.y = ay; o.z = az; o.w = aw;
    *(float4*)&g_h[outSel][(size_t)wi * HID + lane * 4] = o;

    if (doPool) {
        int g = batch[wi];
        float* base = &g_pool[g * HID + lane * 4];
        atomicAdd(base + 0, ax);
        atomicAdd(base + 1, ay);
        atomicAdd(base + 2, az);
        atomicAdd(base + 3, aw);
        if (lane == 0) atomicAdd(&g_pcnt[g], 1.0f);
    }
}

// ---------------- head ----------------
__global__ void k_final(const float* __restrict__ Wl,
                        const float* __restrict__ bl,
                        float* __restrict__ out) {
    int g = blockIdx.x;
    int lane = threadIdx.x;
    float inv = 1.0f / fmaxf(g_pcnt[g], 1.0f);
    float s = 0.f;
    for (int j = lane; j < HID; j += 32)
        s += g_pool[g * HID + j] * inv * Wl[j];
#pragma unroll
    for (int o = 16; o; o >>= 1) s += __shfl_xor_sync(0xFFFFFFFFu, s, o);
    if (lane == 0) out[g] = s + bl[0];
}

// ---------------- launcher: kernel launches ONLY ----------------
extern "C" void kernel_launch(void* const* d_in, const int* in_sizes, int n_in,
                              void* d_out, int out_size) {
    const float* x     = (const float*)d_in[0];
    const int*   ei    = (const int*)d_in[1];    // int32 (JAX x64 disabled)
    const int*   em    = (const int*)d_in[2];
    const int*   batch = (const int*)d_in[3];
    const float* W1 = (const float*)d_in[4];
    const float* b1 = (const float*)d_in[5];
    const float* W2 = (const float*)d_in[6];
    const float* b2 = (const float*)d_in[7];
    const float* W3 = (const float*)d_in[8];
    const float* b3 = (const float*)d_in[9];
    const float* Wl = (const float*)d_in[10];
    const float* bl = (const float*)d_in[11];
    float* out = (float*)d_out;

    const int tb  = 256;
    const int gbN = (NN + tb - 1) / tb;
    const int gbE = (NE + tb - 1) / tb;
    const int gbW = (NN * 32 + tb - 1) / tb;   // warp-per-node
    const int gbG = (NN + 127) / 128;          // gemm: 128 rows/block

    k_zero   <<<gbN, tb>>>();
    k_hist   <<<gbE, tb>>>(ei, em);
    k_scanA  <<<NBLK, 256>>>();
    // GEMM1 independent of CSR build — stays at launch #4 for ncu
    k_gemm   <<<gbG, tb>>>(-1, x, W1);
    k_scanB  <<<1, 256>>>();
    k_scanC  <<<NBLK, 256>>>();                // + fused dinv
    k_scatter<<<gbE, tb>>>(ei, em);

    // layer 1: g_h[0] -> g_h[1] (relu, all edges)
    k_agg <<<gbW, tb>>>(0, 1, b1, 0, 1, 0, batch);
    // layer 2: g_h[1] -> g_h[0] -> g_h[2] (relu, mask==1)
    k_gemm<<<gbG, tb>>>(1, x, W2);
    k_agg <<<gbW, tb>>>(1, 2, b2, 1, 1, 0, batch);
    // layer 3: g_h[2] -> g_h[0] -> g_h[1] (no relu, mask==2) + fused pool
    k_gemm<<<gbG, tb>>>(2, x, W3);
    k_agg <<<gbW, tb>>>(2, 1, b3, 2, 0, 1, batch);

    k_final<<<NG, 32>>>(Wl, bl, out);
}